// round 17
// baseline (speedup 1.0000x reference)
#include <cuda_runtime.h>

typedef unsigned long long u64;

#define BATCH 32
#define SEQ   500
#define DM    128
#define HID   64
#define G3    192        // 3*HID
#define NROW  16000      // BATCH*SEQ
#define NLIB  2145
#define FFD   128

// ---------------- scratch (device globals; no allocation allowed) ----------
__device__ float g_xp0[BATCH * SEQ * G3];    // input projections for GRU L0
__device__ float g_bufA[NROW * HID];         // GRU output
__device__ float g_bufB[NROW * HID];         // SINDy layer 0 output

// ---------------- packed f32x2 helpers ------------------------------------
__device__ __forceinline__ u64 fma2(u64 a, u64 b, u64 c) {
    u64 d; asm("fma.rn.f32x2 %0, %1, %2, %3;" : "=l"(d) : "l"(a), "l"(b), "l"(c)); return d;
}
__device__ __forceinline__ u64 pack2(float x, float y) {
    u64 r; asm("mov.b64 %0, {%1, %2};" : "=l"(r) : "f"(x), "f"(y)); return r;
}
__device__ __forceinline__ u64 bcast2(float x) {
    u64 r; asm("mov.b64 %0, {%1, %1};" : "=l"(r) : "f"(x)); return r;
}
__device__ __forceinline__ void unpack2(u64 v, float& x, float& y) {
    asm("mov.b64 {%0, %1}, %2;" : "=f"(x), "=f"(y) : "l"(v));
}
__device__ __forceinline__ float hadd2(u64 v) { float x, y; unpack2(v, x, y); return x + y; }

// fast activations: ex2.approx + rcp.approx -> ~1e-6 rel err
__device__ __forceinline__ float fast_rcp(float x) {
    float r; asm("rcp.approx.f32 %0, %1;" : "=f"(r) : "f"(x)); return r;
}
__device__ __forceinline__ float fast_ex2(float x) {
    float r; asm("ex2.approx.f32 %0, %1;" : "=f"(r) : "f"(x)); return r;
}
__device__ __forceinline__ float sigf(float v) {
    return fast_rcp(1.0f + fast_ex2(-1.4426950408889634f * v));
}
__device__ __forceinline__ float tanh_fast(float v) {
    float e = fast_ex2(2.8853900817779268f * v);
    return 1.0f - 2.0f * fast_rcp(e + 1.0f);
}

// named barriers
__device__ __forceinline__ void bar_sync(int id, int cnt) {
    asm volatile("bar.sync %0, %1;" :: "r"(id), "r"(cnt) : "memory");
}
__device__ __forceinline__ void bar_arrive(int id, int cnt) {
    asm volatile("bar.arrive %0, %1;" :: "r"(id), "r"(cnt) : "memory");
}

// ============================================================================
// K1: g_xp0[row][g] = bih0[g] + sum_k x[row][k] * Wih0[g][k]
// ============================================================================
__global__ __launch_bounds__(192) void k_xp0(const float* __restrict__ x,
                                             const float* __restrict__ Wih0,
                                             const float* __restrict__ bih0) {
    __shared__ u64 xs[32 * 64];
    const int g = threadIdx.x;
    const u64* x2 = (const u64*)x + (size_t)blockIdx.x * 2048;
    for (int idx = g; idx < 2048; idx += 192) xs[idx] = x2[idx];
    __syncthreads();

    const u64* wp = (const u64*)Wih0 + (size_t)g * 64;
    u64 acc[32];
#pragma unroll
    for (int r = 0; r < 32; r++) acc[r] = 0ull;

    for (int kk = 0; kk < 64; kk++) {
        u64 w = __ldg(&wp[kk]);
#pragma unroll
        for (int r = 0; r < 32; r++) acc[r] = fma2(w, xs[r * 64 + kk], acc[r]);
    }
    const float bias = bih0[g];
    const int row0 = blockIdx.x * 32;
#pragma unroll
    for (int r = 0; r < 32; r++)
        g_xp0[(size_t)(row0 + r) * G3 + g] = hadd2(acc[r]) + bias;
}

// ============================================================================
// K2: decoupled 2-layer GRU — EXACT R12 version (passed). Barrier 5 arrives
// every step (1:1 sync:arrive batch rate — thinning deadlocks; see R14 PM).
// ============================================================================
__global__ __launch_bounds__(384, 1) void k_gru(const float* __restrict__ Whh0,
                                                const float* __restrict__ Wih1,
                                                const float* __restrict__ Whh1,
                                                const float* __restrict__ bhh0,
                                                const float* __restrict__ bih1,
                                                const float* __restrict__ bhh1) {
    __shared__ float ring[4 * 64];    // h0 ring, 4 slots
    __shared__ float h1buf[2 * 64];

    const int t = threadIdx.x;
    const int b = blockIdx.x;
    const float* xp = g_xp0 + (size_t)b * SEQ * G3;
    float* outp = g_bufA + (size_t)b * SEQ * HID;

    u64 w[48];
    float b3[3];
    float b4 = 0.0f;
    float hreg = 0.0f;
    int j, sub;

    if (t < 128) {
        j = t >> 1; sub = t & 1;
        const u64* W0 = (const u64*)Whh0;
#pragma unroll
        for (int g = 0; g < 3; g++) {
#pragma unroll
            for (int k = 0; k < 16; k++)
                w[g * 16 + k] = __ldg(&W0[(size_t)(j + 64 * g) * 32 + sub * 16 + k]);
            b3[g] = bhh0[j + 64 * g];
        }
    } else {
        const int tt = t - 128;
        j = tt >> 2; sub = tt & 3;
        const u64* Wi = (const u64*)Wih1;
        const u64* Wh = (const u64*)Whh1;
#pragma unroll
        for (int g = 0; g < 3; g++) {
#pragma unroll
            for (int k = 0; k < 8; k++) {
                w[g * 16 + k]     = __ldg(&Wi[(size_t)(j + 64 * g) * 32 + sub * 8 + k]);
                w[g * 16 + 8 + k] = __ldg(&Wh[(size_t)(j + 64 * g) * 32 + sub * 8 + k]);
            }
        }
        b3[0] = bih1[j] + bhh1[j];
        b3[1] = bih1[j + 64] + bhh1[j + 64];
        b3[2] = bih1[j + 128];
        b4    = bhh1[j + 128];
    }
    // zero shared state
    if (t < 128) { ring[t] = 0.0f; ring[128 + t] = 0.0f; }
    else if (t < 256) { h1buf[t - 128] = 0.0f; }
    __syncthreads();

    if (t < 128) {
        // ---------------- layer 0 producer ----------------
        float xa0 = xp[j], xa1 = xp[64 + j], xa2 = xp[128 + j];
        const float* x1r = xp + G3;
        float xb0 = x1r[j], xb1 = x1r[64 + j], xb2 = x1r[128 + j];

        for (int s = 0; s < SEQ; s++) {
            float xn0 = 0, xn1 = 0, xn2 = 0;
            if (s + 2 < SEQ) {
                const float* xr = xp + (size_t)(s + 2) * G3;
                xn0 = xr[j]; xn1 = xr[64 + j]; xn2 = xr[128 + j];
            }
            const u64* hb = (const u64*)(ring + ((s + 3) & 3) * 64) + sub * 16;
            u64 a0 = 0, a1 = 0, a2 = 0;
#pragma unroll
            for (int k = 0; k < 16; k++) {
                u64 hv = hb[k];
                a0 = fma2(w[k], hv, a0);
                a1 = fma2(w[16 + k], hv, a1);
                a2 = fma2(w[32 + k], hv, a2);
            }
            float d0 = hadd2(a0), d1 = hadd2(a1), d2 = hadd2(a2);
            d0 += __shfl_xor_sync(0xffffffffu, d0, 1);
            d1 += __shfl_xor_sync(0xffffffffu, d1, 1);
            d2 += __shfl_xor_sync(0xffffffffu, d2, 1);
            float rg = sigf(xa0 + d0 + b3[0]);
            float zg = sigf(xa1 + d1 + b3[1]);
            float ng = tanh_fast(xa2 + rg * (d2 + b3[2]));
            hreg = (1.0f - zg) * ng + zg * hreg;

            if (s >= 4) bar_sync(5, 384);          // slot s%4 free (L1 done with s-4)
            if (sub == 0) ring[(s & 3) * 64 + j] = hreg;
            bar_sync(3, 128);                       // in-group: drain STS
            bar_arrive(1, 384);                     // publish h0[s]

            xa0 = xb0; xa1 = xb1; xa2 = xb2;
            xb0 = xn0; xb1 = xn1; xb2 = xn2;
        }
    } else {
        // ---------------- layer 1 consumer ----------------
        for (int u = 0; u < SEQ; u++) {
            bar_sync(1, 384);                       // h0[u] ready
            const u64* hb0 = (const u64*)(ring + (u & 3) * 64) + sub * 8;
            const u64* hb1 = (const u64*)(h1buf + ((u & 1) ^ 1) * 64) + sub * 8;
            u64 a0 = 0, a1 = 0, a2i = 0, a2h = 0;
#pragma unroll
            for (int k = 0; k < 8; k++) {
                u64 h0v = hb0[k], h1v = hb1[k];
                a0  = fma2(w[k],      h0v, a0);
                a0  = fma2(w[8 + k],  h1v, a0);
                a1  = fma2(w[16 + k], h0v, a1);
                a1  = fma2(w[24 + k], h1v, a1);
                a2i = fma2(w[32 + k], h0v, a2i);
                a2h = fma2(w[40 + k], h1v, a2h);
            }
            float d0 = hadd2(a0), d1 = hadd2(a1);
            float di = hadd2(a2i), dh = hadd2(a2h);
            d0 += __shfl_xor_sync(0xffffffffu, d0, 1);
            d1 += __shfl_xor_sync(0xffffffffu, d1, 1);
            di += __shfl_xor_sync(0xffffffffu, di, 1);
            dh += __shfl_xor_sync(0xffffffffu, dh, 1);
            d0 += __shfl_xor_sync(0xffffffffu, d0, 2);
            d1 += __shfl_xor_sync(0xffffffffu, d1, 2);
            di += __shfl_xor_sync(0xffffffffu, di, 2);
            dh += __shfl_xor_sync(0xffffffffu, dh, 2);
            float rg = sigf(d0 + b3[0]);
            float zg = sigf(d1 + b3[1]);
            float ng = tanh_fast(di + b3[2] + rg * (dh + b4));
            hreg = (1.0f - zg) * ng + zg * hreg;

            bar_arrive(5, 384);                     // done reading ring slot u%4
            if (sub == 0) {
                h1buf[(u & 1) * 64 + j] = hreg;
                outp[(size_t)u * HID + j] = hreg;
            }
            bar_sync(2, 256);                       // in-group recurrence barrier
        }
    }
}

// ============================================================================
// K3: fused SINDy layer — 125 blocks x 512 threads (occupancy 2x vs R12).
// Phase A: 4x4 thread tiles (8 fma2/kk/thread), double-buffered Theta/coef.
// Phase C: 4-way column split (r = t>>2, p = t&3), 4-lane shfl LN2.
// ============================================================================
#define SINDY_SMEM 169216

__global__ __launch_bounds__(512, 1) void k_sindy(int layer, float* __restrict__ out_ext,
                                                  const float* __restrict__ coef,
                                                  const float* __restrict__ g1,
                                                  const float* __restrict__ b1n,
                                                  const float* __restrict__ W1,
                                                  const float* __restrict__ bf1,
                                                  const float* __restrict__ W2,
                                                  const float* __restrict__ bf2,
                                                  const float* __restrict__ g2,
                                                  const float* __restrict__ b2n) {
    extern __shared__ char sm[];
    float* zT  = (float*)sm;                        // [65][132]
    float* th0 = (float*)(sm + 34320);
    float* th1 = (float*)(sm + 68112);
    float* cc0 = (float*)(sm + 101904);
    float* cc1 = (float*)(sm + 118288);
    unsigned char* ta = (unsigned char*)(sm + 134672);
    float* s1f = (float*)sm;                        // [128][66] (phase C)
    float* w1s = (float*)(sm + 33792);
    float* w2t = (float*)(sm + 67584);
    float* h1s = (float*)(sm + 101376);             // [128][129]
    float* par = (float*)(sm + 167424);

    const float* in = (layer == 0) ? g_bufA : g_bufB;
    float* outp     = (layer == 0) ? g_bufB : out_ext;
    float* tail     = out_ext + NROW * HID;
    const int final_layer = (layer == 1);

    const int t = threadIdx.x;
    const int row0 = blockIdx.x * 128;

    // ---- load z transposed (+ ones row 64), params, index table ----
    const float* inb = in + (size_t)row0 * HID;
    for (int idx = t; idx < 128 * 64; idx += 512) {
        int r = idx >> 6, c = idx & 63;
        zT[c * 132 + r] = inb[idx];
    }
    if (t < 128) zT[64 * 132 + t] = 1.0f;

    if (t < 448) {
        int idx = t;
        float v;
        if      (idx < 64)  v = g1[idx];
        else if (idx < 128) v = b1n[idx - 64];
        else if (idx < 192) v = g2[idx - 128];
        else if (idx < 256) v = b2n[idx - 192];
        else if (idx < 384) v = bf1[idx - 256];
        else                v = bf2[idx - 384];
        par[idx] = v;
    }

    for (int k = t; k < NLIB; k += 512) {
        int i, j;
        if (k == 0)      { i = 64; j = 64; }
        else if (k < 65) { i = k - 1; j = 64; }
        else {
            int q = k - 65;
            i = (int)floorf((129.0f - sqrtf(16641.0f - 8.0f * (float)q)) * 0.5f);
            if (i < 0) i = 0; if (i > 63) i = 63;
            while (i < 63 && ((i + 1) * 64 - (i + 1) * i / 2) <= q) i++;
            while (i > 0 && (i * 64 - i * (i - 1) / 2) > q) i--;
            j = i + (q - (i * 64 - i * (i - 1) / 2));
        }
        ta[2 * k]     = (unsigned char)i;
        ta[2 * k + 1] = (unsigned char)j;
    }
    __syncthreads();

    // ---- phase A: upd = Theta @ coef, 4x4 register tiles, double-buffered ----
    const int tx = t & 15, ty = t >> 4;     // ty 0..31
    const int c0 = tx * 4, r0 = ty * 4;

    u64 acc[8];     // acc[rp*4 + jc]: rows (r0+2rp, r0+2rp+1), col c0+jc
#pragma unroll
    for (int u = 0; u < 8; u++) acc[u] = 0ull;

    // prologue: stage chunk 0
    {
        const float4* src4 = (const float4*)coef;
        float4* dst4 = (float4*)cc0;
#pragma unroll
        for (int ii = 0; ii < 2; ii++) dst4[t + ii * 512] = src4[t + ii * 512];
#pragma unroll
        for (int ii = 0; ii < 4; ii++) {
            int idx = t + ii * 512;
            int kk = idx >> 5, rq = idx & 31;
            int i = ta[2 * kk], j = ta[2 * kk + 1];
            float4 zi = *(const float4*)(zT + i * 132 + rq * 4);
            float4 zj = *(const float4*)(zT + j * 132 + rq * 4);
            float4 o = make_float4(zi.x * zj.x, zi.y * zj.y, zi.z * zj.z, zi.w * zj.w);
            *(float4*)(th0 + kk * 132 + rq * 4) = o;
        }
    }
    __syncthreads();

    for (int cn = 0; cn * 64 < NLIB; cn++) {
        const float* thc = (cn & 1) ? th1 : th0;
        const float* ccc = (cn & 1) ? cc1 : cc0;
        float* thn = (cn & 1) ? th0 : th1;
        float* ccn = (cn & 1) ? cc0 : cc1;
        const int kb_n = (cn + 1) * 64;
        const int klen_n = (kb_n < NLIB) ? ((NLIB - kb_n < 64) ? (NLIB - kb_n) : 64) : 0;
        const int klen   = (NLIB - cn * 64 < 64) ? (NLIB - cn * 64) : 64;

        // prefetch next coef chunk into registers
        float4 cr[2];
        if (klen_n > 0) {
            const float4* src4 = (const float4*)(coef + (size_t)kb_n * 64);
            const int lim = klen_n * 16;
#pragma unroll
            for (int ii = 0; ii < 2; ii++) {
                int idx = t + ii * 512;
                if (idx < lim) cr[ii] = src4[idx];
            }
        }

        // main fma loop
#pragma unroll 4
        for (int kk = 0; kk < klen; kk++) {
            ulonglong2 q0 = *(const ulonglong2*)(thc + kk * 132 + r0);   // rows r0..r0+3
            float4 cf = *(const float4*)(ccc + kk * 64 + c0);
            u64 b0 = bcast2(cf.x), b1 = bcast2(cf.y), b2 = bcast2(cf.z), b3 = bcast2(cf.w);
            acc[0] = fma2(q0.x, b0, acc[0]);  acc[1] = fma2(q0.x, b1, acc[1]);
            acc[2] = fma2(q0.x, b2, acc[2]);  acc[3] = fma2(q0.x, b3, acc[3]);
            acc[4] = fma2(q0.y, b0, acc[4]);  acc[5] = fma2(q0.y, b1, acc[5]);
            acc[6] = fma2(q0.y, b2, acc[6]);  acc[7] = fma2(q0.y, b3, acc[7]);
        }

        // stage next chunk
        if (klen_n > 0) {
            float4* dst4 = (float4*)ccn;
            const int lim = klen_n * 16;
#pragma unroll
            for (int ii = 0; ii < 2; ii++) {
                int idx = t + ii * 512;
                if (idx < lim) dst4[idx] = cr[ii];
            }
#pragma unroll
            for (int ii = 0; ii < 4; ii++) {
                int idx = t + ii * 512;
                int kk = idx >> 5, rq = idx & 31;
                if (kk < klen_n) {
                    int i = ta[2 * (kb_n + kk)], j = ta[2 * (kb_n + kk) + 1];
                    float4 zi = *(const float4*)(zT + i * 132 + rq * 4);
                    float4 zj = *(const float4*)(zT + j * 132 + rq * 4);
                    float4 o = make_float4(zi.x * zj.x, zi.y * zj.y, zi.z * zj.z, zi.w * zj.w);
                    *(float4*)(thn + kk * 132 + rq * 4) = o;
                }
            }
        }
        __syncthreads();
    }

    // ---- phase B: residual (reads zT), then write s1f (aliases zT) ----
    float vals[16];   // vals[rr*4 + jc] = row r0+rr, col c0+jc
#pragma unroll
    for (int rp = 0; rp < 2; rp++)
#pragma unroll
        for (int jc = 0; jc < 4; jc++) {
            float v0, v1; unpack2(acc[rp * 4 + jc], v0, v1);
            vals[(2 * rp) * 4 + jc]     = v0 + zT[(c0 + jc) * 132 + r0 + 2 * rp];
            vals[(2 * rp + 1) * 4 + jc] = v1 + zT[(c0 + jc) * 132 + r0 + 2 * rp + 1];
        }
    __syncthreads();
#pragma unroll
    for (int rr = 0; rr < 4; rr++)
#pragma unroll
        for (int jc = 0; jc < 4; jc++)
            s1f[(r0 + rr) * 66 + c0 + jc] = vals[rr * 4 + jc];
    __syncthreads();

    // LN1 (threads 0-127) while others stage W1 / W2^T
    if (t < 128) {
        float* rowp = s1f + t * 66;
        float s = 0.0f, s2 = 0.0f;
        for (int c = 0; c < 64; c++) { float v = rowp[c]; s += v; s2 += v * v; }
        float m = s * (1.0f / 64.0f);
        float inv = rsqrtf(s2 * (1.0f / 64.0f) - m * m + 1e-5f);
        for (int c = 0; c < 64; c++)
            rowp[c] = (rowp[c] - m) * inv * par[c] + par[64 + c];
    } else {
        const int t2 = t - 128;
        for (int idx = t2; idx < 128 * 64; idx += 384) {
            int f = idx >> 6, c = idx & 63;
            w1s[f * 66 + c] = W1[idx];
        }
        for (int idx = t2; idx < 64 * 128; idx += 384) {
            int c = idx >> 7, f = idx & 127;
            w2t[f * 66 + c] = W2[idx];
        }
    }
    __syncthreads();

    // ---- phase C1: FF1 -> gelu -> h1s  (r = t>>2, p = t&3: 32 f each) ----
    const int r = t >> 2;
    const int p = t & 3;
    {
        u64 s1r[32];
        const u64* srow = (const u64*)(s1f + r * 66);
#pragma unroll
        for (int cc = 0; cc < 32; cc++) s1r[cc] = srow[cc];
        for (int f0 = 0; f0 < 32; f0++) {
            int f = p * 32 + f0;
            u64 a = 0ull;
            const u64* wrow = (const u64*)(w1s + f * 66);
#pragma unroll
            for (int cc = 0; cc < 32; cc++) a = fma2(s1r[cc], wrow[cc], a);
            float v = hadd2(a) + par[256 + f];
            h1s[r * 129 + f] = 0.5f * v * (1.0f + erff(v * 0.70710678118654752f));
        }
    }
    __syncthreads();

    // ---- phase C2: FF2 + residual + LN2 (4-lane shfl LN) ----
    {
        u64 acc3[8];
#pragma unroll
        for (int u = 0; u < 8; u++) {
            int c = p * 16 + 2 * u;
            acc3[u] = pack2(s1f[r * 66 + c] + par[384 + c],
                            s1f[r * 66 + c + 1] + par[384 + c + 1]);
        }
        const float* hrow = h1s + r * 129;
        for (int f = 0; f < 128; f++) {
            u64 a2 = bcast2(hrow[f]);
            const u64* wrow = (const u64*)(w2t + f * 66) + p * 8;
#pragma unroll
            for (int u = 0; u < 8; u++) acc3[u] = fma2(a2, wrow[u], acc3[u]);
        }
        float ov[16];
        float s = 0.0f, s2 = 0.0f;
#pragma unroll
        for (int u = 0; u < 8; u++) {
            float x0, x1; unpack2(acc3[u], x0, x1);
            ov[2 * u] = x0; ov[2 * u + 1] = x1;
            s += x0 + x1; s2 += x0 * x0 + x1 * x1;
        }
        s  += __shfl_xor_sync(0xffffffffu, s, 1);
        s2 += __shfl_xor_sync(0xffffffffu, s2, 1);
        s  += __shfl_xor_sync(0xffffffffu, s, 2);
        s2 += __shfl_xor_sync(0xffffffffu, s2, 2);
        float m = s * (1.0f / 64.0f);
        float inv = rsqrtf(s2 * (1.0f / 64.0f) - m * m + 1e-5f);
#pragma unroll
        for (int u = 0; u < 16; u++)
            ov[u] = (ov[u] - m) * inv * par[128 + p * 16 + u] + par[192 + p * 16 + u];

        const int grow = row0 + r;
        float2* op2 = (float2*)(outp + (size_t)grow * HID + p * 16);
#pragma unroll
        for (int u = 0; u < 8; u++) op2[u] = make_float2(ov[2 * u], ov[2 * u + 1]);

        if (final_layer && (grow % SEQ) == (SEQ - 1)) {
            float* tp = tail + (grow / SEQ) * HID + p * 16;
#pragma unroll
            for (int u = 0; u < 16; u++) tp[u] = ov[u];
        }
    }
}

// ============================================================================
extern "C" void kernel_launch(void* const* d_in, const int* in_sizes, int n_in,
                              void* d_out, int out_size) {
    const float* x     = (const float*)d_in[0];
    const float* Wih0  = (const float*)d_in[1];
    const float* Whh0  = (const float*)d_in[2];
    const float* bih0  = (const float*)d_in[3];
    const float* bhh0  = (const float*)d_in[4];
    const float* Wih1  = (const float*)d_in[5];
    const float* Whh1  = (const float*)d_in[6];
    const float* bih1  = (const float*)d_in[7];
    const float* bhh1  = (const float*)d_in[8];
    const float* coeffs= (const float*)d_in[9];
    const float* ln1_g = (const float*)d_in[10];
    const float* ln1_b = (const float*)d_in[11];
    const float* W1    = (const float*)d_in[12];
    const float* b1    = (const float*)d_in[13];
    const float* W2    = (const float*)d_in[14];
    const float* b2    = (const float*)d_in[15];
    const float* ln2_g = (const float*)d_in[16];
    const float* ln2_b = (const float*)d_in[17];
    float* out = (float*)d_out;

    cudaFuncSetAttribute(k_sindy, cudaFuncAttributeMaxDynamicSharedMemorySize, SINDY_SMEM);

    k_xp0<<<500, 192>>>(x, Wih0, bih0);
    k_gru<<<32, 384>>>(Whh0, Wih1, Whh1, bhh0, bih1, bhh1);

    for (int l = 0; l < 2; l++) {
        k_sindy<<<125, 512, SINDY_SMEM>>>(l, out,
            coeffs + (size_t)l * NLIB * HID,
            ln1_g + l * HID, ln1_b + l * HID,
            W1 + (size_t)l * FFD * HID, b1 + l * FFD,
            W2 + (size_t)l * HID * FFD, b2 + l * HID,
            ln2_g + l * HID, ln2_b + l * HID);
    }
}